// round 7
// baseline (speedup 1.0000x reference)
#include <cuda_runtime.h>
#include <cstdint>

// ---------------- scratch (no dynamic allocation allowed) ----------------
__device__ float g_qkv[4096 * 3072];   // (B*C, 3*D) = x @ w_qkv + b_qkv
__device__ float g_attn[4096 * 1024];  // (B*C, D)   = attention output

// round-to-nearest fp32 -> tf32 (kept as fp32 bit pattern with low mantissa zeroed)
__device__ __forceinline__ float f2tf32(float x) {
    uint32_t u;
    asm("cvt.rna.tf32.f32 %0, %1;" : "=r"(u) : "f"(x));
    return __uint_as_float(u);
}
__device__ __forceinline__ uint32_t fau(float x) { return __float_as_uint(x); }

// D += A(16x8,row) * B(8x8,col) in tf32, fp32 accumulate
__device__ __forceinline__ void mma8(float c[4], const uint32_t a[4], const uint32_t b[2]) {
    asm("mma.sync.aligned.m16n8k8.row.col.f32.tf32.tf32.f32 "
        "{%0,%1,%2,%3}, {%4,%5,%6,%7}, {%8,%9}, {%0,%1,%2,%3};"
        : "+f"(c[0]), "+f"(c[1]), "+f"(c[2]), "+f"(c[3])
        : "r"(a[0]), "r"(a[1]), "r"(a[2]), "r"(a[3]),
          "r"(b[0]), "r"(b[1]));
}

// =====================================================================
// GEMM: C[M,N] = A[M,K] @ B[K,N] + bias   (fp32 I/O, tf32x3 compute)
// Block tile 128x128, K-tile 32. 256 threads = 8 warps (2 x 4), warp
// tile 64x32. Split each input into hi+lo tf32; acc = hh + hl + lh.
// smem strides: A stride 36 (==4 mod 32), B stride 136 (==8 mod 32)
// -> conflict-free fragment gathers.
// =====================================================================
__global__ __launch_bounds__(256, 1)
void gemm_tf32x3(const float* __restrict__ A, const float* __restrict__ B,
                 const float* __restrict__ bias, float* __restrict__ C,
                 int M, int N, int K)
{
    (void)M;
    extern __shared__ float sm[];
    constexpr int ASTR = 36;
    constexpr int BSTR = 136;
    float* As_hi = sm;
    float* As_lo = As_hi + 128 * ASTR;
    float* Bs_hi = As_lo + 128 * ASTR;
    float* Bs_lo = Bs_hi + 32 * BSTR;

    const int tid  = threadIdx.x;
    const int lane = tid & 31;
    const int warp = tid >> 5;
    const int g = lane >> 2, t = lane & 3;
    const int wm = warp >> 2;   // 0..1  (64 rows each)
    const int wn = warp & 3;    // 0..3  (32 cols each)
    const int bm0 = blockIdx.y * 128;
    const int bn0 = blockIdx.x * 128;

    float acc[4][4][4];
#pragma unroll
    for (int i = 0; i < 4; i++)
#pragma unroll
        for (int j = 0; j < 4; j++)
#pragma unroll
            for (int e = 0; e < 4; e++) acc[i][j][e] = 0.f;

    for (int kt = 0; kt < K; kt += 32) {
        __syncthreads();
        // ---- load A tile 128x32, split hi/lo ----
#pragma unroll
        for (int j = 0; j < 4; j++) {
            int fid = tid + j * 256;
            int row = fid >> 3;
            int c0  = (fid & 7) * 4;
            const float4 v = *(const float4*)(A + (size_t)(bm0 + row) * K + kt + c0);
            float4 hi, lo;
            hi.x = f2tf32(v.x); lo.x = f2tf32(v.x - hi.x);
            hi.y = f2tf32(v.y); lo.y = f2tf32(v.y - hi.y);
            hi.z = f2tf32(v.z); lo.z = f2tf32(v.z - hi.z);
            hi.w = f2tf32(v.w); lo.w = f2tf32(v.w - hi.w);
            *(float4*)(As_hi + row * ASTR + c0) = hi;
            *(float4*)(As_lo + row * ASTR + c0) = lo;
        }
        // ---- load B tile 32x128, split hi/lo ----
#pragma unroll
        for (int j = 0; j < 4; j++) {
            int fid = tid + j * 256;
            int row = fid >> 5;
            int c0  = (fid & 31) * 4;
            const float4 v = *(const float4*)(B + (size_t)(kt + row) * N + bn0 + c0);
            float4 hi, lo;
            hi.x = f2tf32(v.x); lo.x = f2tf32(v.x - hi.x);
            hi.y = f2tf32(v.y); lo.y = f2tf32(v.y - hi.y);
            hi.z = f2tf32(v.z); lo.z = f2tf32(v.z - hi.z);
            hi.w = f2tf32(v.w); lo.w = f2tf32(v.w - hi.w);
            *(float4*)(Bs_hi + row * BSTR + c0) = hi;
            *(float4*)(Bs_lo + row * BSTR + c0) = lo;
        }
        __syncthreads();

#pragma unroll
        for (int ks = 0; ks < 4; ks++) {
            uint32_t ah[4][4], al[4][4], bh[4][2], bl[4][2];
#pragma unroll
            for (int mt = 0; mt < 4; mt++) {
                const float* p = As_hi + (wm * 64 + mt * 16 + g) * ASTR + ks * 8 + t;
                const float* q = As_lo + (wm * 64 + mt * 16 + g) * ASTR + ks * 8 + t;
                ah[mt][0] = fau(p[0]);
                ah[mt][1] = fau(p[8 * ASTR]);
                ah[mt][2] = fau(p[4]);
                ah[mt][3] = fau(p[8 * ASTR + 4]);
                al[mt][0] = fau(q[0]);
                al[mt][1] = fau(q[8 * ASTR]);
                al[mt][2] = fau(q[4]);
                al[mt][3] = fau(q[8 * ASTR + 4]);
            }
#pragma unroll
            for (int nt = 0; nt < 4; nt++) {
                const float* p = Bs_hi + (ks * 8 + t) * BSTR + wn * 32 + nt * 8 + g;
                const float* q = Bs_lo + (ks * 8 + t) * BSTR + wn * 32 + nt * 8 + g;
                bh[nt][0] = fau(p[0]);
                bh[nt][1] = fau(p[4 * BSTR]);
                bl[nt][0] = fau(q[0]);
                bl[nt][1] = fau(q[4 * BSTR]);
            }
#pragma unroll
            for (int mt = 0; mt < 4; mt++)
#pragma unroll
                for (int nt = 0; nt < 4; nt++) {
                    mma8(acc[mt][nt], ah[mt], bh[nt]);
                    mma8(acc[mt][nt], ah[mt], bl[nt]);
                    mma8(acc[mt][nt], al[mt], bh[nt]);
                }
        }
    }

    // ---- epilogue: + bias, store fp32 ----
#pragma unroll
    for (int mt = 0; mt < 4; mt++) {
        int r0 = bm0 + wm * 64 + mt * 16 + g;
#pragma unroll
        for (int nt = 0; nt < 4; nt++) {
            int col = bn0 + wn * 32 + nt * 8 + 2 * t;
            float bb0 = bias[col], bb1 = bias[col + 1];
            *(float2*)(C + (size_t)r0 * N + col) =
                make_float2(acc[mt][nt][0] + bb0, acc[mt][nt][1] + bb1);
            *(float2*)(C + (size_t)(r0 + 8) * N + col) =
                make_float2(acc[mt][nt][2] + bb0, acc[mt][nt][3] + bb1);
        }
    }
}

// =====================================================================
// Flash attention per (b, h, 64-query-row tile). 128 threads = 4 warps,
// each warp owns 16 query rows. K-tiles of 64 keys. tf32 MMA, online
// softmax in fragment registers, P staged via warp-private smem.
// qkv layout: [(b*1024+c)*3072 + tt*1024 + h*64 + d], tt in {q,k,v}.
// =====================================================================
__global__ __launch_bounds__(128, 1)
void attn_flash_tf32(const float* __restrict__ qkv, float* __restrict__ out)
{
    extern __shared__ float sm[];
    constexpr int QS = 68;   // ==4 mod 32
    constexpr int KSs = 68;  // ==4 mod 32
    constexpr int VSs = 72;  // ==8 mod 32
    constexpr int PSs = 68;  // ==4 mod 32
    float* Qs = sm;
    float* Ks = Qs + 64 * QS;
    float* Vs = Ks + 64 * KSs;
    float* Ps = Vs + 64 * VSs;

    const int tid  = threadIdx.x;
    const int lane = tid & 31;
    const int warp = tid >> 5;
    const int g = lane >> 2, t = lane & 3;

    const int qt = blockIdx.x;        // 0..15 (query tile)
    const int b  = blockIdx.y >> 4;   // 0..3
    const int h  = blockIdx.y & 15;   // 0..15

    const size_t tok0 = (size_t)b * 1024;

    // ---- load Q tile (pre-scaled by 1/8 = exact, then rna->tf32) ----
#pragma unroll
    for (int j = 0; j < 8; j++) {
        int fid = tid + j * 128;
        int row = fid >> 4;
        int c0  = (fid & 15) * 4;
        const float4 v = *(const float4*)(qkv + (tok0 + qt * 64 + row) * 3072 + h * 64 + c0);
        float4 w;
        w.x = f2tf32(v.x * 0.125f);
        w.y = f2tf32(v.y * 0.125f);
        w.z = f2tf32(v.z * 0.125f);
        w.w = f2tf32(v.w * 0.125f);
        *(float4*)(Qs + row * QS + c0) = w;
    }

    float m_r[2] = {-1e30f, -1e30f};
    float l_r[2] = {0.f, 0.f};
    float oacc[8][4];
#pragma unroll
    for (int nt = 0; nt < 8; nt++)
#pragma unroll
        for (int e = 0; e < 4; e++) oacc[nt][e] = 0.f;

    const int qrow = warp * 16 + g;

    for (int kc = 0; kc < 16; kc++) {
        __syncthreads();   // protects Ks/Vs reuse across iterations
        // ---- load K and V tiles (64 keys x 64 dims), rna->tf32 ----
#pragma unroll
        for (int j = 0; j < 8; j++) {
            int fid = tid + j * 128;
            int row = fid >> 4;
            int c0  = (fid & 15) * 4;
            const float* base = qkv + (tok0 + kc * 64 + row) * 3072 + h * 64 + c0;
            float4 kv = *(const float4*)(base + 1024);
            float4 vv = *(const float4*)(base + 2048);
            float4 wk, wv;
            wk.x = f2tf32(kv.x); wk.y = f2tf32(kv.y); wk.z = f2tf32(kv.z); wk.w = f2tf32(kv.w);
            wv.x = f2tf32(vv.x); wv.y = f2tf32(vv.y); wv.z = f2tf32(vv.z); wv.w = f2tf32(vv.w);
            *(float4*)(Ks + row * KSs + c0) = wk;
            *(float4*)(Vs + row * VSs + c0) = wv;
        }
        __syncthreads();

        // ---- S(16x64) = Q_tile @ K_tile^T ----
        float sacc[8][4];
#pragma unroll
        for (int nt = 0; nt < 8; nt++)
#pragma unroll
            for (int e = 0; e < 4; e++) sacc[nt][e] = 0.f;

#pragma unroll
        for (int ks = 0; ks < 8; ks++) {
            uint32_t a[4];
            const float* pa = Qs + qrow * QS + ks * 8 + t;
            a[0] = fau(pa[0]);
            a[1] = fau(pa[8 * QS]);
            a[2] = fau(pa[4]);
            a[3] = fau(pa[8 * QS + 4]);
#pragma unroll
            for (int nt = 0; nt < 8; nt++) {
                uint32_t bb[2];
                const float* pb = Ks + (nt * 8 + g) * KSs + ks * 8 + t;  // B[k=d][n=key]
                bb[0] = fau(pb[0]);
                bb[1] = fau(pb[4]);
                mma8(sacc[nt], a, bb);
            }
        }

        // ---- online softmax over the 2 rows this lane covers ----
#pragma unroll
        for (int r = 0; r < 2; r++) {
            const int e0 = 2 * r;
            float mx = sacc[0][e0];
#pragma unroll
            for (int nt = 0; nt < 8; nt++) {
                mx = fmaxf(mx, sacc[nt][e0]);
                mx = fmaxf(mx, sacc[nt][e0 + 1]);
            }
            mx = fmaxf(mx, __shfl_xor_sync(0xffffffffu, mx, 1));
            mx = fmaxf(mx, __shfl_xor_sync(0xffffffffu, mx, 2));
            const float m_new = fmaxf(m_r[r], mx);
            const float alpha = __expf(m_r[r] - m_new);
            float s = 0.f;
#pragma unroll
            for (int nt = 0; nt < 8; nt++) {
                float p0 = __expf(sacc[nt][e0]     - m_new);
                float p1 = __expf(sacc[nt][e0 + 1] - m_new);
                sacc[nt][e0]     = p0;
                sacc[nt][e0 + 1] = p1;
                s += p0 + p1;
            }
            s += __shfl_xor_sync(0xffffffffu, s, 1);
            s += __shfl_xor_sync(0xffffffffu, s, 2);
            l_r[r] = l_r[r] * alpha + s;
            m_r[r] = m_new;
#pragma unroll
            for (int nt = 0; nt < 8; nt++) {
                oacc[nt][e0]     *= alpha;
                oacc[nt][e0 + 1] *= alpha;
            }
        }

        // ---- stage P (accumulator layout -> A-fragment layout via smem) ----
#pragma unroll
        for (int nt = 0; nt < 8; nt++) {
            *(float2*)(Ps + (size_t)qrow * PSs + nt * 8 + 2 * t) =
                make_float2(f2tf32(sacc[nt][0]), f2tf32(sacc[nt][1]));
            *(float2*)(Ps + (size_t)(qrow + 8) * PSs + nt * 8 + 2 * t) =
                make_float2(f2tf32(sacc[nt][2]), f2tf32(sacc[nt][3]));
        }
        __syncwarp();   // P is warp-private; only intra-warp visibility needed

        // ---- O += P @ V ----
#pragma unroll
        for (int ks = 0; ks < 8; ks++) {
            uint32_t a[4];
            const float* pa = Ps + qrow * PSs + ks * 8 + t;
            a[0] = fau(pa[0]);
            a[1] = fau(pa[8 * PSs]);
            a[2] = fau(pa[4]);
            a[3] = fau(pa[8 * PSs + 4]);
#pragma unroll
            for (int nt = 0; nt < 8; nt++) {
                uint32_t bb[2];
                const float* pb = Vs + (ks * 8 + t) * VSs + nt * 8 + g;  // B[k=key][n=d]
                bb[0] = fau(pb[0]);
                bb[1] = fau(pb[4 * VSs]);
                mma8(oacc[nt], a, bb);
            }
        }
    }

    // ---- normalize and store: out[(b*1024+c)*1024 + h*64 + d] ----
    const float inv0 = 1.f / l_r[0];
    const float inv1 = 1.f / l_r[1];
    const size_t row0 = tok0 + qt * 64 + qrow;
#pragma unroll
    for (int nt = 0; nt < 8; nt++) {
        int col = h * 64 + nt * 8 + 2 * t;
        *(float2*)(out + row0 * 1024 + col) =
            make_float2(oacc[nt][0] * inv0, oacc[nt][1] * inv0);
        *(float2*)(out + (row0 + 8) * 1024 + col) =
            make_float2(oacc[nt][2] * inv1, oacc[nt][3] * inv1);
    }
}

// =====================================================================
extern "C" void kernel_launch(void* const* d_in, const int* in_sizes, int n_in,
                              void* d_out, int out_size)
{
    (void)in_sizes; (void)n_in; (void)out_size;
    const float* x      = (const float*)d_in[0];
    const float* w_qkv  = (const float*)d_in[1];
    const float* b_qkv  = (const float*)d_in[2];
    const float* w_proj = (const float*)d_in[3];
    const float* b_proj = (const float*)d_in[4];
    float* out = (float*)d_out;

    float* qkv  = nullptr;
    float* attn = nullptr;
    cudaGetSymbolAddress((void**)&qkv,  g_qkv);
    cudaGetSymbolAddress((void**)&attn, g_attn);

    constexpr int GEMM_SMEM = (2 * 128 * 36 + 2 * 32 * 136) * 4;       // 71680 B
    constexpr int ATTN_SMEM = (64 * 68 * 3 + 64 * 72) * 4;             // 70656 B
    cudaFuncSetAttribute(gemm_tf32x3,     cudaFuncAttributeMaxDynamicSharedMemorySize, GEMM_SMEM);
    cudaFuncSetAttribute(attn_flash_tf32, cudaFuncAttributeMaxDynamicSharedMemorySize, ATTN_SMEM);

    // 1) qkv = x @ w_qkv + b_qkv        (4096 x 3072 x 1024)
    gemm_tf32x3<<<dim3(3072 / 128, 4096 / 128), 256, GEMM_SMEM>>>(
        x, w_qkv, b_qkv, qkv, 4096, 3072, 1024);

    // 2) attention: 16 q-tiles x (B*H = 64)
    attn_flash_tf32<<<dim3(16, 64), 128, ATTN_SMEM>>>(qkv, attn);

    // 3) out = attn @ w_proj + b_proj   (4096 x 1024 x 1024)
    gemm_tf32x3<<<dim3(1024 / 128, 4096 / 128), 256, GEMM_SMEM>>>(
        attn, w_proj, b_proj, out, 4096, 1024, 1024);
}

// round 8
// speedup vs baseline: 1.4595x; 1.4595x over previous
#include <cuda_runtime.h>
#include <cstdint>

// ---------------- scratch (no dynamic allocation allowed) ----------------
__device__ float g_qkv[4096 * 3072];   // (B*C, 3*D) = x @ w_qkv + b_qkv
__device__ float g_attn[4096 * 1024];  // (B*C, D)   = attention output

// round-to-nearest fp32 -> tf32 (kept as fp32 bit pattern, low mantissa zeroed)
__device__ __forceinline__ float f2tf32(float x) {
    uint32_t u;
    asm("cvt.rna.tf32.f32 %0, %1;" : "=r"(u) : "f"(x));
    return __uint_as_float(u);
}
__device__ __forceinline__ uint32_t fau(float x) { return __float_as_uint(x); }

// D += A(16x8,row) * B(8x8,col) in tf32, fp32 accumulate
__device__ __forceinline__ void mma8(float c[4], const uint32_t a[4], const uint32_t b[2]) {
    asm("mma.sync.aligned.m16n8k8.row.col.f32.tf32.tf32.f32 "
        "{%0,%1,%2,%3}, {%4,%5,%6,%7}, {%8,%9}, {%0,%1,%2,%3};"
        : "+f"(c[0]), "+f"(c[1]), "+f"(c[2]), "+f"(c[3])
        : "r"(a[0]), "r"(a[1]), "r"(a[2]), "r"(a[3]),
          "r"(b[0]), "r"(b[1]));
}

__device__ __forceinline__ void cp_async16(float* smem, const float* gmem) {
    uint32_t s = (uint32_t)__cvta_generic_to_shared(smem);
    asm volatile("cp.async.cg.shared.global [%0], [%1], 16;\n" :: "r"(s), "l"(gmem));
}
__device__ __forceinline__ void cp_commit() {
    asm volatile("cp.async.commit_group;\n" ::: "memory");
}
template <int N>
__device__ __forceinline__ void cp_wait() {
    asm volatile("cp.async.wait_group %0;\n" :: "n"(N) : "memory");
}

// =====================================================================
// GEMM: C[M,N] = A[M,K] @ B[K,N] + bias   (fp32 I/O, tf32x2 compute)
// Block tile 128x128, K-tile 32, 256 threads = 8 warps (2x4), warp
// tile 64x32. Raw fp32 staged in smem via cp.async, double buffered.
// Precision: acc = rna(A) * (Bhi + Blo)  -> only A-rounding error
// survives (~2.8e-4 rms), B is exact to ~2^-22.
// smem strides: A 36 (==4 mod 32), B 136 (==8 mod 32): conflict-free
// fragment gathers.
// =====================================================================
__global__ __launch_bounds__(256, 2)
void gemm_tf32x2(const float* __restrict__ A, const float* __restrict__ B,
                 const float* __restrict__ bias, float* __restrict__ C,
                 int N, int K)
{
    extern __shared__ float sm[];
    constexpr int ASTR = 36;
    constexpr int BSTR = 136;
    constexpr int ASZ = 128 * ASTR;        // 4608 floats
    constexpr int BSZ = 32 * BSTR;         // 4352 floats
    constexpr int STAGE = ASZ + BSZ;       // 8960 floats = 35840 B / stage

    const int tid  = threadIdx.x;
    const int lane = tid & 31;
    const int warp = tid >> 5;
    const int g = lane >> 2, t = lane & 3;
    const int wm = warp >> 2;   // 0..1  (64 rows)
    const int wn = warp & 3;    // 0..3  (32 cols)
    const int bm0 = blockIdx.y * 128;
    const int bn0 = blockIdx.x * 128;

    const int arow = tid >> 3;          // 0..31 (strided +32 x4)
    const int ac0  = (tid & 7) * 4;
    const int brow = tid >> 5;          // 0..7  (strided +8 x4)
    const int bc0  = (tid & 31) * 4;

    auto load_tiles = [&](int kt, int s) {
        float* As = sm + s * STAGE;
        float* Bs = As + ASZ;
#pragma unroll
        for (int j = 0; j < 4; j++) {
            int row = arow + j * 32;
            cp_async16(As + row * ASTR + ac0,
                       A + (size_t)(bm0 + row) * K + kt + ac0);
        }
#pragma unroll
        for (int j = 0; j < 4; j++) {
            int row = brow + j * 8;
            cp_async16(Bs + row * BSTR + bc0,
                       B + (size_t)(kt + row) * N + bn0 + bc0);
        }
        cp_commit();
    };

    float acc[4][4][4];
#pragma unroll
    for (int i = 0; i < 4; i++)
#pragma unroll
        for (int j = 0; j < 4; j++)
#pragma unroll
            for (int e = 0; e < 4; e++) acc[i][j][e] = 0.f;

    load_tiles(0, 0);

    const int NT = K >> 5;   // K/32 iterations
    for (int it = 0; it < NT; it++) {
        // prefetch next tile into the other buffer (safe: trailing barrier of
        // iteration it-1 guarantees all warps finished computing on it)
        if (it + 1 < NT) {
            load_tiles((it + 1) * 32, (it + 1) & 1);
            cp_wait<1>();          // group `it` complete
        } else {
            cp_wait<0>();
        }
        __syncthreads();

        const float* As = sm + (it & 1) * STAGE;
        const float* Bs = As + ASZ;

#pragma unroll
        for (int ks = 0; ks < 4; ks++) {
            uint32_t ah[4][4], bh[4][2], bl[4][2];
#pragma unroll
            for (int mt = 0; mt < 4; mt++) {
                const float* p = As + (wm * 64 + mt * 16 + g) * ASTR + ks * 8 + t;
                ah[mt][0] = fau(f2tf32(p[0]));
                ah[mt][1] = fau(f2tf32(p[8 * ASTR]));
                ah[mt][2] = fau(f2tf32(p[4]));
                ah[mt][3] = fau(f2tf32(p[8 * ASTR + 4]));
            }
#pragma unroll
            for (int nt = 0; nt < 4; nt++) {
                const float* p = Bs + (ks * 8 + t) * BSTR + wn * 32 + nt * 8 + g;
                float b0 = p[0], b1 = p[4 * BSTR];
                float h0 = f2tf32(b0), h1 = f2tf32(b1);
                bh[nt][0] = fau(h0);
                bh[nt][1] = fau(h1);
                bl[nt][0] = fau(f2tf32(b0 - h0));
                bl[nt][1] = fau(f2tf32(b1 - h1));
            }
#pragma unroll
            for (int mt = 0; mt < 4; mt++)
#pragma unroll
                for (int nt = 0; nt < 4; nt++) {
                    mma8(acc[mt][nt], ah[mt], bh[nt]);
                    mma8(acc[mt][nt], ah[mt], bl[nt]);
                }
        }
        __syncthreads();   // protect buffer (it&1) from next iteration's prefetch
    }

    // ---- epilogue: + bias, store fp32 ----
#pragma unroll
    for (int mt = 0; mt < 4; mt++) {
        int r0 = bm0 + wm * 64 + mt * 16 + g;
#pragma unroll
        for (int nt = 0; nt < 4; nt++) {
            int col = bn0 + wn * 32 + nt * 8 + 2 * t;
            float bb0 = bias[col], bb1 = bias[col + 1];
            *(float2*)(C + (size_t)r0 * N + col) =
                make_float2(acc[mt][nt][0] + bb0, acc[mt][nt][1] + bb1);
            *(float2*)(C + (size_t)(r0 + 8) * N + col) =
                make_float2(acc[mt][nt][2] + bb0, acc[mt][nt][3] + bb1);
        }
    }
}

// =====================================================================
// Flash attention per (b, h, 64-query-row tile). Unchanged from the
// passing round-7 kernel (isolate the GEMM change).
// qkv layout: [(b*1024+c)*3072 + tt*1024 + h*64 + d], tt in {q,k,v}.
// =====================================================================
__global__ __launch_bounds__(128, 1)
void attn_flash_tf32(const float* __restrict__ qkv, float* __restrict__ out)
{
    extern __shared__ float sm[];
    constexpr int QS = 68;   // ==4 mod 32
    constexpr int KSs = 68;  // ==4 mod 32
    constexpr int VSs = 72;  // ==8 mod 32
    constexpr int PSs = 68;  // ==4 mod 32
    float* Qs = sm;
    float* Ks = Qs + 64 * QS;
    float* Vs = Ks + 64 * KSs;
    float* Ps = Vs + 64 * VSs;

    const int tid  = threadIdx.x;
    const int lane = tid & 31;
    const int warp = tid >> 5;
    const int g = lane >> 2, t = lane & 3;

    const int qt = blockIdx.x;        // 0..15 (query tile)
    const int b  = blockIdx.y >> 4;   // 0..3
    const int h  = blockIdx.y & 15;   // 0..15

    const size_t tok0 = (size_t)b * 1024;

    // ---- load Q tile (pre-scaled by 1/8 = exact, then rna->tf32) ----
#pragma unroll
    for (int j = 0; j < 8; j++) {
        int fid = tid + j * 128;
        int row = fid >> 4;
        int c0  = (fid & 15) * 4;
        const float4 v = *(const float4*)(qkv + (tok0 + qt * 64 + row) * 3072 + h * 64 + c0);
        float4 w;
        w.x = f2tf32(v.x * 0.125f);
        w.y = f2tf32(v.y * 0.125f);
        w.z = f2tf32(v.z * 0.125f);
        w.w = f2tf32(v.w * 0.125f);
        *(float4*)(Qs + row * QS + c0) = w;
    }

    float m_r[2] = {-1e30f, -1e30f};
    float l_r[2] = {0.f, 0.f};
    float oacc[8][4];
#pragma unroll
    for (int nt = 0; nt < 8; nt++)
#pragma unroll
        for (int e = 0; e < 4; e++) oacc[nt][e] = 0.f;

    const int qrow = warp * 16 + g;

    for (int kc = 0; kc < 16; kc++) {
        __syncthreads();   // protects Ks/Vs reuse across iterations
#pragma unroll
        for (int j = 0; j < 8; j++) {
            int fid = tid + j * 128;
            int row = fid >> 4;
            int c0  = (fid & 15) * 4;
            const float* base = qkv + (tok0 + kc * 64 + row) * 3072 + h * 64 + c0;
            float4 kv = *(const float4*)(base + 1024);
            float4 vv = *(const float4*)(base + 2048);
            float4 wk, wv;
            wk.x = f2tf32(kv.x); wk.y = f2tf32(kv.y); wk.z = f2tf32(kv.z); wk.w = f2tf32(kv.w);
            wv.x = f2tf32(vv.x); wv.y = f2tf32(vv.y); wv.z = f2tf32(vv.z); wv.w = f2tf32(vv.w);
            *(float4*)(Ks + row * KSs + c0) = wk;
            *(float4*)(Vs + row * VSs + c0) = wv;
        }
        __syncthreads();

        // ---- S(16x64) = Q_tile @ K_tile^T ----
        float sacc[8][4];
#pragma unroll
        for (int nt = 0; nt < 8; nt++)
#pragma unroll
            for (int e = 0; e < 4; e++) sacc[nt][e] = 0.f;

#pragma unroll
        for (int ks = 0; ks < 8; ks++) {
            uint32_t a[4];
            const float* pa = Qs + qrow * QS + ks * 8 + t;
            a[0] = fau(pa[0]);
            a[1] = fau(pa[8 * QS]);
            a[2] = fau(pa[4]);
            a[3] = fau(pa[8 * QS + 4]);
#pragma unroll
            for (int nt = 0; nt < 8; nt++) {
                uint32_t bb[2];
                const float* pb = Ks + (nt * 8 + g) * KSs + ks * 8 + t;
                bb[0] = fau(pb[0]);
                bb[1] = fau(pb[4]);
                mma8(sacc[nt], a, bb);
            }
        }

        // ---- online softmax ----
#pragma unroll
        for (int r = 0; r < 2; r++) {
            const int e0 = 2 * r;
            float mx = sacc[0][e0];
#pragma unroll
            for (int nt = 0; nt < 8; nt++) {
                mx = fmaxf(mx, sacc[nt][e0]);
                mx = fmaxf(mx, sacc[nt][e0 + 1]);
            }
            mx = fmaxf(mx, __shfl_xor_sync(0xffffffffu, mx, 1));
            mx = fmaxf(mx, __shfl_xor_sync(0xffffffffu, mx, 2));
            const float m_new = fmaxf(m_r[r], mx);
            const float alpha = __expf(m_r[r] - m_new);
            float s = 0.f;
#pragma unroll
            for (int nt = 0; nt < 8; nt++) {
                float p0 = __expf(sacc[nt][e0]     - m_new);
                float p1 = __expf(sacc[nt][e0 + 1] - m_new);
                sacc[nt][e0]     = p0;
                sacc[nt][e0 + 1] = p1;
                s += p0 + p1;
            }
            s += __shfl_xor_sync(0xffffffffu, s, 1);
            s += __shfl_xor_sync(0xffffffffu, s, 2);
            l_r[r] = l_r[r] * alpha + s;
            m_r[r] = m_new;
#pragma unroll
            for (int nt = 0; nt < 8; nt++) {
                oacc[nt][e0]     *= alpha;
                oacc[nt][e0 + 1] *= alpha;
            }
        }

        // ---- stage P via warp-private smem (re-fragment) ----
#pragma unroll
        for (int nt = 0; nt < 8; nt++) {
            *(float2*)(Ps + (size_t)qrow * PSs + nt * 8 + 2 * t) =
                make_float2(f2tf32(sacc[nt][0]), f2tf32(sacc[nt][1]));
            *(float2*)(Ps + (size_t)(qrow + 8) * PSs + nt * 8 + 2 * t) =
                make_float2(f2tf32(sacc[nt][2]), f2tf32(sacc[nt][3]));
        }
        __syncwarp();

        // ---- O += P @ V ----
#pragma unroll
        for (int ks = 0; ks < 8; ks++) {
            uint32_t a[4];
            const float* pa = Ps + qrow * PSs + ks * 8 + t;
            a[0] = fau(pa[0]);
            a[1] = fau(pa[8 * PSs]);
            a[2] = fau(pa[4]);
            a[3] = fau(pa[8 * PSs + 4]);
#pragma unroll
            for (int nt = 0; nt < 8; nt++) {
                uint32_t bb[2];
                const float* pb = Vs + (ks * 8 + t) * VSs + nt * 8 + g;
                bb[0] = fau(pb[0]);
                bb[1] = fau(pb[4 * VSs]);
                mma8(oacc[nt], a, bb);
            }
        }
    }

    // ---- normalize and store ----
    const float inv0 = 1.f / l_r[0];
    const float inv1 = 1.f / l_r[1];
    const size_t row0 = tok0 + qt * 64 + qrow;
#pragma unroll
    for (int nt = 0; nt < 8; nt++) {
        int col = h * 64 + nt * 8 + 2 * t;
        *(float2*)(out + row0 * 1024 + col) =
            make_float2(oacc[nt][0] * inv0, oacc[nt][1] * inv0);
        *(float2*)(out + (row0 + 8) * 1024 + col) =
            make_float2(oacc[nt][2] * inv1, oacc[nt][3] * inv1);
    }
}

// =====================================================================
extern "C" void kernel_launch(void* const* d_in, const int* in_sizes, int n_in,
                              void* d_out, int out_size)
{
    (void)in_sizes; (void)n_in; (void)out_size;
    const float* x      = (const float*)d_in[0];
    const float* w_qkv  = (const float*)d_in[1];
    const float* b_qkv  = (const float*)d_in[2];
    const float* w_proj = (const float*)d_in[3];
    const float* b_proj = (const float*)d_in[4];
    float* out = (float*)d_out;

    float* qkv  = nullptr;
    float* attn = nullptr;
    cudaGetSymbolAddress((void**)&qkv,  g_qkv);
    cudaGetSymbolAddress((void**)&attn, g_attn);

    constexpr int GEMM_SMEM = 2 * (128 * 36 + 32 * 136) * 4;          // 71680 B
    constexpr int ATTN_SMEM = (64 * 68 * 3 + 64 * 72) * 4;            // 70656 B
    cudaFuncSetAttribute(gemm_tf32x2,     cudaFuncAttributeMaxDynamicSharedMemorySize, GEMM_SMEM);
    cudaFuncSetAttribute(attn_flash_tf32, cudaFuncAttributeMaxDynamicSharedMemorySize, ATTN_SMEM);

    // 1) qkv = x @ w_qkv + b_qkv        (4096 x 3072 x 1024)
    gemm_tf32x2<<<dim3(3072 / 128, 4096 / 128), 256, GEMM_SMEM>>>(
        x, w_qkv, b_qkv, qkv, 3072, 1024);

    // 2) attention: 16 q-tiles x (B*H = 64)
    attn_flash_tf32<<<dim3(16, 64), 128, ATTN_SMEM>>>(qkv, attn);

    // 3) out = attn @ w_proj + b_proj   (4096 x 1024 x 1024)
    gemm_tf32x2<<<dim3(1024 / 128, 4096 / 128), 256, GEMM_SMEM>>>(
        attn, w_proj, b_proj, out, 1024, 1024);
}